// round 9
// baseline (speedup 1.0000x reference)
#include <cuda_runtime.h>
#include <cuda_bf16.h>
#include <cstdint>

// DotInteract: out[b] = concat(dense[b] (128), triu(C C^T) (378)),
// C = [dense[b]; sparse[b,0..25]] (27x128 fp32). B = 32768, OUTW = 506.
//
// One warp per sample, Gram via mma.sync.m16n8k16 bf16.
// fp32 = bf16 hi + lo; D = hi.hi^T + hi.lo^T + lo.hi^T (err ~3e-6).
// R9: cp.async.cg double-buffered raw fp32 staging decouples DRAM latency
// from the convert->STS->LDSM->MMA chain at zero register cost. Each lane
// reads back only slots it wrote, so no sync between wait_group and convert.

#define THREADS 128
#define WPC     4                    // warps = samples per CTA
#define OUTW    506
#define TSTRIDE 80                   // tile row bytes (conflict-free LDSM)
#define TBYTES  (32 * TSTRIDE)       // 2560 per split tile
#define TILES   (2 * TBYTES)         // hi + lo = 5120 (also epilogue stage)
#define RAWSTR  144                  // raw row stride bytes (36 floats)
#define RAWB    (27 * RAWSTR)        // 3888 per raw chunk buffer
#define WSTR    (TILES + 2 * RAWB)   // 12896 per warp
#define SMEMTOT (WPC * WSTR)         // 51584

__device__ __forceinline__ uint32_t smem_u32(const void* p) {
    uint32_t a;
    asm("{ .reg .u64 t; cvta.to.shared.u64 t, %1; cvt.u32.u64 %0, t; }" : "=r"(a) : "l"(p));
    return a;
}
__device__ __forceinline__ uint32_t pack_bf16x2(float lo, float hi) {
    uint32_t r;  // d = { cvt(hi)=upper16 | cvt(lo)=lower16 }
    asm("cvt.rn.bf16x2.f32 %0, %1, %2;" : "=r"(r) : "f"(hi), "f"(lo));
    return r;
}
__device__ __forceinline__ float bf_lo(uint32_t p) { return __uint_as_float(p << 16); }
__device__ __forceinline__ float bf_hi(uint32_t p) { return __uint_as_float(p & 0xFFFF0000u); }

__device__ __forceinline__ void cpasync16(uint32_t dst, const float4* src, bool pred) {
    asm volatile("{\n\t.reg .pred p;\n\tsetp.ne.u32 p, %2, 0;\n\t"
                 "@p cp.async.cg.shared.global [%0], [%1], 16;\n\t}"
                 :: "r"(dst), "l"(src), "r"((uint32_t)pred));
}
#define CP_COMMIT() asm volatile("cp.async.commit_group;" ::: "memory")
#define CP_WAIT1()  asm volatile("cp.async.wait_group 1;"  ::: "memory")
#define CP_WAIT0()  asm volatile("cp.async.wait_group 0;"  ::: "memory")

__device__ __forceinline__ void ldsm4(uint32_t* r, uint32_t addr) {
    asm volatile("ldmatrix.sync.aligned.m8n8.x4.shared.b16 {%0,%1,%2,%3}, [%4];"
                 : "=r"(r[0]), "=r"(r[1]), "=r"(r[2]), "=r"(r[3]) : "r"(addr));
}
__device__ __forceinline__ void mma16816(float* d, const uint32_t* a,
                                         uint32_t b0, uint32_t b1) {
    asm volatile("mma.sync.aligned.m16n8k16.row.col.f32.bf16.bf16.f32 "
                 "{%0,%1,%2,%3}, {%4,%5,%6,%7}, {%8,%9}, {%0,%1,%2,%3};"
                 : "+f"(d[0]), "+f"(d[1]), "+f"(d[2]), "+f"(d[3])
                 : "r"(a[0]), "r"(a[1]), "r"(a[2]), "r"(a[3]), "r"(b0), "r"(b1));
}
__device__ __forceinline__ void do_pair(float* c00, float* c01, float* c02, float* c03,
                                        float* c12, float* c13,
                                        const uint32_t* S0, const uint32_t* S1,
                                        const uint32_t* T0, const uint32_t* T1) {
    mma16816(c00, S0, T0[0], T0[2]);
    mma16816(c01, S0, T0[1], T0[3]);
    mma16816(c02, S0, T1[0], T1[2]);
    mma16816(c03, S0, T1[1], T1[3]);
    mma16816(c12, S1, T1[0], T1[2]);
    mma16816(c13, S1, T1[1], T1[3]);
}

extern __shared__ char smem[];

__global__ void __launch_bounds__(THREADS, 4)
dot_interact_mma(const float4* __restrict__ dense4,
                 const float4* __restrict__ sparse4,
                 float* __restrict__ out, int B)
{
    const int warp = threadIdx.x >> 5;
    const int lane = threadIdx.x & 31;
    const int b    = blockIdx.x * WPC + warp;
    if (b >= B) return;

    const uint32_t hiBase  = smem_u32(smem) + warp * WSTR;
    const uint32_t loBase  = hiBase + TBYTES;
    const uint32_t rawBase = hiBase + TILES;       // raw0; raw1 at +RAWB

    // ---- zero pad tile rows 27..31 (once; first syncwarp orders vs LDSM) ----
    #pragma unroll
    for (int it = 0; it < 3; it++) {
        int idx = it * 32 + lane;                  // need < 80
        if (idx < 80) {
            int t   = idx >= 40;
            int rem = idx - t * 40;
            uint32_t ad = (t ? loBase : hiBase) + (27 + (rem >> 3)) * TSTRIDE + (rem & 7) * 8;
            asm volatile("st.shared.v2.b32 [%0], {%1, %1};" :: "r"(ad), "r"(0u));
        }
    }

    // ---- affine plan: it = 0..6, row r = r0 + 4*it, c4 = lane&7 ----
    const int r0 = lane >> 3;                      // 0..3
    const int c4 = lane & 7;
    const bool dlane   = (r0 == 0);                // it==0 reads dense
    const bool tail_ok = (lane < 24);              // it==6 rows 24..26 only
    const float4* dptr = dense4 + (long long)b * 32 + c4;
    const float4* sptr = sparse4 + ((long long)b * 26 + (r0 - 1)) * 32 + c4;
    const uint32_t rOff0 = (uint32_t)(r0 * RAWSTR + c4 * 16);
    const uint32_t sOff0 = (uint32_t)(r0 * TSTRIDE + c4 * 8);

    float c00[4] = {0,0,0,0}, c01[4] = {0,0,0,0}, c02[4] = {0,0,0,0};
    float c03[4] = {0,0,0,0}, c12[4] = {0,0,0,0}, c13[4] = {0,0,0,0};

    float2* out2 = reinterpret_cast<float2*>(out) + (long long)b * (OUTW / 2);

    const int lrow = ((lane >> 3) & 1) * 8 + (lane & 7);
    const int lu   = lane >> 4;

    // ---- prologue: async-load chunks 0 and 1 ----
    #pragma unroll
    for (int pc = 0; pc < 2; pc++) {
        uint32_t rb = rawBase + pc * RAWB;
        #pragma unroll
        for (int it = 0; it < 7; it++) {
            bool pred = (it < 6) | tail_ok;
            const float4* src = (it == 0 && dlane) ? (dptr + pc * 8)
                                                   : (sptr + pc * 8 + it * 128);
            cpasync16(rb + rOff0 + it * (4 * RAWSTR), src, pred);
        }
        CP_COMMIT();
    }

    #pragma unroll
    for (int kc = 0; kc < 4; kc++) {
        if (kc < 3) { CP_WAIT1(); } else { CP_WAIT0(); }
        const uint32_t rb = rawBase + (kc & 1) * RAWB;

        // ---- convert: LDS own raw slots -> split bf16 hi/lo -> STS tiles ----
        #pragma unroll
        for (int it = 0; it < 7; it++) {
            if (it == 6 && !tail_ok) break;
            float4 v;
            asm volatile("ld.shared.v4.b32 {%0,%1,%2,%3}, [%4];"
                         : "=f"(v.x), "=f"(v.y), "=f"(v.z), "=f"(v.w)
                         : "r"(rb + rOff0 + it * (4 * RAWSTR)));
            uint32_t h01 = pack_bf16x2(v.x, v.y);
            uint32_t h23 = pack_bf16x2(v.z, v.w);
            uint32_t l01 = pack_bf16x2(v.x - bf_lo(h01), v.y - bf_hi(h01));
            uint32_t l23 = pack_bf16x2(v.z - bf_lo(h23), v.w - bf_hi(h23));
            uint32_t so = sOff0 + it * (4 * TSTRIDE);
            asm volatile("st.shared.v2.b32 [%0], {%1, %2};"
                         :: "r"(hiBase + so), "r"(h01), "r"(h23));
            asm volatile("st.shared.v2.b32 [%0], {%1, %2};"
                         :: "r"(loBase + so), "r"(l01), "r"(l23));
            if (it == 0 && dlane) {                // lanes 0..7: dense passthrough
                out2[kc * 16 + lane * 2]     = make_float2(v.x, v.y);
                out2[kc * 16 + lane * 2 + 1] = make_float2(v.z, v.w);
            }
        }

        // ---- refill freed buffer with chunk kc+2 (after all raw reads) ----
        if (kc < 2) {
            #pragma unroll
            for (int it = 0; it < 7; it++) {
                bool pred = (it < 6) | tail_ok;
                const float4* src = (it == 0 && dlane) ? (dptr + (kc + 2) * 8)
                                                       : (sptr + (kc + 2) * 8 + it * 128);
                cpasync16(rb + rOff0 + it * (4 * RAWSTR), src, pred);
            }
            CP_COMMIT();
        }
        __syncwarp();

        // ---- compute: 2 k-steps x (4 LDSM.x4 + 18 HMMA) ----
        #pragma unroll
        for (int ks = 0; ks < 2; ks++) {
            uint32_t off0 = (uint32_t)(lrow * TSTRIDE + (2 * ks + lu) * 16);
            uint32_t H0[4], H1[4], L0[4], L1[4];
            ldsm4(H0, hiBase + off0);
            ldsm4(H1, hiBase + off0 + 16 * TSTRIDE);
            ldsm4(L0, loBase + off0);
            ldsm4(L1, loBase + off0 + 16 * TSTRIDE);
            do_pair(c00, c01, c02, c03, c12, c13, H0, H1, H0, H1);  // hi.hi
            do_pair(c00, c01, c02, c03, c12, c13, H0, H1, L0, L1);  // hi.lo
            do_pair(c00, c01, c02, c03, c12, c13, L0, L1, H0, H1);  // lo.hi
        }
        __syncwarp();   // WAR before tile restaging
    }

    // ---- epilogue: frags -> smem gram[32][33], then triu scatter ----
    float* gstage = reinterpret_cast<float*>(smem + warp * WSTR);   // reuse tiles
    {
        const int fr = lane >> 2;
        const int fc = 2 * (lane & 3);
        float* t[6] = {c00, c01, c02, c03, c12, c13};
        const int mi[6] = {0, 0, 0, 0, 16, 16};
        const int nj[6] = {0, 8, 16, 24, 16, 24};
        #pragma unroll
        for (int q = 0; q < 6; q++) {
            int r = mi[q] + fr, c = nj[q] + fc;
            gstage[r * 33 + c]           = t[q][0];
            gstage[r * 33 + c + 1]       = t[q][1];
            gstage[(r + 8) * 33 + c]     = t[q][2];
            gstage[(r + 8) * 33 + c + 1] = t[q][3];
        }
    }
    __syncwarp();

    {   // lane j writes gram[i][j] for i <= j; per-i stores coalesced
        float* orow = out + (long long)b * OUTW + 128;
        #pragma unroll 1
        for (int i = 0; i < 27; i++) {
            if (lane < 27 && i <= lane) {
                orow[26 * i - (i * (i - 1)) / 2 + lane] = gstage[i * 33 + lane];
            }
        }
    }
}

extern "C" void kernel_launch(void* const* d_in, const int* in_sizes, int n_in,
                              void* d_out, int out_size)
{
    const float4* dense4  = (const float4*)d_in[0];
    const float4* sparse4 = (const float4*)d_in[1];
    float*        out     = (float*)d_out;

    int B = in_sizes[0] / 128;
    int grid = (B + WPC - 1) / WPC;

    cudaFuncSetAttribute(dot_interact_mma,
                         cudaFuncAttributeMaxDynamicSharedMemorySize, SMEMTOT);
    dot_interact_mma<<<grid, THREADS, SMEMTOT>>>(dense4, sparse4, out, B);
    (void)n_in; (void)out_size;
}

// round 10
// speedup vs baseline: 1.1114x; 1.1114x over previous
#include <cuda_runtime.h>
#include <cuda_bf16.h>
#include <cstdint>

// DotInteract: out[b] = concat(dense[b] (128), triu(C C^T) (378)),
// C = [dense[b]; sparse[b,0..25]] (27x128 fp32). B = 32768, OUTW = 506.
//
// One warp per sample, Gram via mma.sync.m16n8k16 bf16.
// fp32 = bf16 hi + lo; D = hi.hi^T + hi.lo^T + lo.hi^T (err ~3e-6).
// R10: SINGLE-buffer cp.async raw staging (R9's latency decoupling at R8's
// occupancy). Refill of chunk kc+1 is issued right after the convert reads
// chunk kc (per-lane WAR safe: each lane overwrites only slots it already
// read), so the next chunk's DRAM latency hides under the MMA phase.

#define THREADS 128
#define WPC     4                    // warps = samples per CTA
#define OUTW    506
#define TSTRIDE 80                   // tile row bytes (conflict-free LDSM)
#define TBYTES  (32 * TSTRIDE)       // 2560 per split tile
#define TILES   (2 * TBYTES)         // hi + lo = 5120 (also epilogue stage)
#define RAWSTR  144                  // raw row stride bytes (36 floats)
#define RAWB    (27 * RAWSTR)        // 3888: one raw chunk buffer
#define WSTR    (TILES + RAWB)       // 9008 per warp
#define SMEMTOT (WPC * WSTR)         // 36032 per CTA -> 6 CTAs/SM

__device__ __forceinline__ uint32_t smem_u32(const void* p) {
    uint32_t a;
    asm("{ .reg .u64 t; cvta.to.shared.u64 t, %1; cvt.u32.u64 %0, t; }" : "=r"(a) : "l"(p));
    return a;
}
__device__ __forceinline__ uint32_t pack_bf16x2(float lo, float hi) {
    uint32_t r;  // d = { cvt(hi)=upper16 | cvt(lo)=lower16 }
    asm("cvt.rn.bf16x2.f32 %0, %1, %2;" : "=r"(r) : "f"(hi), "f"(lo));
    return r;
}
__device__ __forceinline__ float bf_lo(uint32_t p) { return __uint_as_float(p << 16); }
__device__ __forceinline__ float bf_hi(uint32_t p) { return __uint_as_float(p & 0xFFFF0000u); }

__device__ __forceinline__ void cpasync16(uint32_t dst, const float4* src, bool pred) {
    asm volatile("{\n\t.reg .pred p;\n\tsetp.ne.u32 p, %2, 0;\n\t"
                 "@p cp.async.cg.shared.global [%0], [%1], 16;\n\t}"
                 :: "r"(dst), "l"(src), "r"((uint32_t)pred));
}
#define CP_COMMIT() asm volatile("cp.async.commit_group;" ::: "memory")
#define CP_WAIT0()  asm volatile("cp.async.wait_group 0;"  ::: "memory")

__device__ __forceinline__ void ldsm4(uint32_t* r, uint32_t addr) {
    asm volatile("ldmatrix.sync.aligned.m8n8.x4.shared.b16 {%0,%1,%2,%3}, [%4];"
                 : "=r"(r[0]), "=r"(r[1]), "=r"(r[2]), "=r"(r[3]) : "r"(addr));
}
__device__ __forceinline__ void mma16816(float* d, const uint32_t* a,
                                         uint32_t b0, uint32_t b1) {
    asm volatile("mma.sync.aligned.m16n8k16.row.col.f32.bf16.bf16.f32 "
                 "{%0,%1,%2,%3}, {%4,%5,%6,%7}, {%8,%9}, {%0,%1,%2,%3};"
                 : "+f"(d[0]), "+f"(d[1]), "+f"(d[2]), "+f"(d[3])
                 : "r"(a[0]), "r"(a[1]), "r"(a[2]), "r"(a[3]), "r"(b0), "r"(b1));
}
__device__ __forceinline__ void do_pair(float* c00, float* c01, float* c02, float* c03,
                                        float* c12, float* c13,
                                        const uint32_t* S0, const uint32_t* S1,
                                        const uint32_t* T0, const uint32_t* T1) {
    mma16816(c00, S0, T0[0], T0[2]);
    mma16816(c01, S0, T0[1], T0[3]);
    mma16816(c02, S0, T1[0], T1[2]);
    mma16816(c03, S0, T1[1], T1[3]);
    mma16816(c12, S1, T1[0], T1[2]);
    mma16816(c13, S1, T1[1], T1[3]);
}

extern __shared__ char smem[];

__global__ void __launch_bounds__(THREADS, 6)
dot_interact_mma(const float4* __restrict__ dense4,
                 const float4* __restrict__ sparse4,
                 float* __restrict__ out, int B)
{
    const int warp = threadIdx.x >> 5;
    const int lane = threadIdx.x & 31;
    const int b    = blockIdx.x * WPC + warp;
    if (b >= B) return;

    const uint32_t hiBase  = smem_u32(smem) + warp * WSTR;
    const uint32_t loBase  = hiBase + TBYTES;
    const uint32_t rawBase = hiBase + TILES;

    // ---- zero pad tile rows 27..31 (once) ----
    #pragma unroll
    for (int it = 0; it < 3; it++) {
        int idx = it * 32 + lane;                  // need < 80
        if (idx < 80) {
            int t   = idx >= 40;
            int rem = idx - t * 40;
            uint32_t ad = (t ? loBase : hiBase) + (27 + (rem >> 3)) * TSTRIDE + (rem & 7) * 8;
            asm volatile("st.shared.v2.b32 [%0], {%1, %1};" :: "r"(ad), "r"(0u));
        }
    }

    // ---- affine plan: it = 0..6, row r = r0 + 4*it, c4 = lane&7 ----
    const int r0 = lane >> 3;                      // 0..3
    const int c4 = lane & 7;
    const bool dlane   = (r0 == 0);                // it==0 reads dense
    const bool tail_ok = (lane < 24);              // it==6 rows 24..26 only
    const float4* dptr = dense4 + (long long)b * 32 + c4;
    const float4* sptr = sparse4 + ((long long)b * 26 + (r0 - 1)) * 32 + c4;
    const uint32_t rOff0 = (uint32_t)(r0 * RAWSTR + c4 * 16);
    const uint32_t sOff0 = (uint32_t)(r0 * TSTRIDE + c4 * 8);

    float c00[4] = {0,0,0,0}, c01[4] = {0,0,0,0}, c02[4] = {0,0,0,0};
    float c03[4] = {0,0,0,0}, c12[4] = {0,0,0,0}, c13[4] = {0,0,0,0};

    float2* out2 = reinterpret_cast<float2*>(out) + (long long)b * (OUTW / 2);

    const int lrow = ((lane >> 3) & 1) * 8 + (lane & 7);
    const int lu   = lane >> 4;

    // ---- prologue: async-load chunk 0 ----
    #pragma unroll
    for (int it = 0; it < 7; it++) {
        bool pred = (it < 6) | tail_ok;
        const float4* src = (it == 0 && dlane) ? dptr : (sptr + it * 128);
        cpasync16(rawBase + rOff0 + it * (4 * RAWSTR), src, pred);
    }
    CP_COMMIT();

    #pragma unroll
    for (int kc = 0; kc < 4; kc++) {
        CP_WAIT0();     // own lane's slots now valid (lane reads only own slots)

        // ---- convert: LDS own raw slots -> split bf16 hi/lo -> STS tiles ----
        #pragma unroll
        for (int it = 0; it < 7; it++) {
            if (it == 6 && !tail_ok) break;
            float4 v;
            asm volatile("ld.shared.v4.b32 {%0,%1,%2,%3}, [%4];"
                         : "=f"(v.x), "=f"(v.y), "=f"(v.z), "=f"(v.w)
                         : "r"(rawBase + rOff0 + it * (4 * RAWSTR)));
            uint32_t h01 = pack_bf16x2(v.x, v.y);
            uint32_t h23 = pack_bf16x2(v.z, v.w);
            uint32_t l01 = pack_bf16x2(v.x - bf_lo(h01), v.y - bf_hi(h01));
            uint32_t l23 = pack_bf16x2(v.z - bf_lo(h23), v.w - bf_hi(h23));
            uint32_t so = sOff0 + it * (4 * TSTRIDE);
            asm volatile("st.shared.v2.b32 [%0], {%1, %2};"
                         :: "r"(hiBase + so), "r"(h01), "r"(h23));
            asm volatile("st.shared.v2.b32 [%0], {%1, %2};"
                         :: "r"(loBase + so), "r"(l01), "r"(l23));
            if (it == 0 && dlane) {                // lanes 0..7: dense passthrough
                out2[kc * 16 + lane * 2]     = make_float2(v.x, v.y);
                out2[kc * 16 + lane * 2 + 1] = make_float2(v.z, v.w);
            }
        }

        // ---- refill same buffer with chunk kc+1 (per-lane WAR safe) ----
        if (kc < 3) {
            #pragma unroll
            for (int it = 0; it < 7; it++) {
                bool pred = (it < 6) | tail_ok;
                const float4* src = (it == 0 && dlane) ? (dptr + (kc + 1) * 8)
                                                       : (sptr + (kc + 1) * 8 + it * 128);
                cpasync16(rawBase + rOff0 + it * (4 * RAWSTR), src, pred);
            }
            CP_COMMIT();
        }
        __syncwarp();   // STS tiles visible to whole warp before LDSM

        // ---- compute: 2 k-steps x (4 LDSM.x4 + 18 HMMA); loads overlap this ----
        #pragma unroll
        for (int ks = 0; ks < 2; ks++) {
            uint32_t off0 = (uint32_t)(lrow * TSTRIDE + (2 * ks + lu) * 16);
            uint32_t H0[4], H1[4], L0[4], L1[4];
            ldsm4(H0, hiBase + off0);
            ldsm4(H1, hiBase + off0 + 16 * TSTRIDE);
            ldsm4(L0, loBase + off0);
            ldsm4(L1, loBase + off0 + 16 * TSTRIDE);
            do_pair(c00, c01, c02, c03, c12, c13, H0, H1, H0, H1);  // hi.hi
            do_pair(c00, c01, c02, c03, c12, c13, H0, H1, L0, L1);  // hi.lo
            do_pair(c00, c01, c02, c03, c12, c13, L0, L1, H0, H1);  // lo.hi
        }
        __syncwarp();   // WAR before tile restaging
    }

    // ---- epilogue: frags -> smem gram[32][33], then triu scatter ----
    float* gstage = reinterpret_cast<float*>(smem + warp * WSTR);   // reuse tiles
    {
        const int fr = lane >> 2;
        const int fc = 2 * (lane & 3);
        float* t[6] = {c00, c01, c02, c03, c12, c13};
        const int mi[6] = {0, 0, 0, 0, 16, 16};
        const int nj[6] = {0, 8, 16, 24, 16, 24};
        #pragma unroll
        for (int q = 0; q < 6; q++) {
            int r = mi[q] + fr, c = nj[q] + fc;
            gstage[r * 33 + c]           = t[q][0];
            gstage[r * 33 + c + 1]       = t[q][1];
            gstage[(r + 8) * 33 + c]     = t[q][2];
            gstage[(r + 8) * 33 + c + 1] = t[q][3];
        }
    }
    __syncwarp();

    {   // lane j writes gram[i][j] for i <= j; per-i stores coalesced
        float* orow = out + (long long)b * OUTW + 128;
        #pragma unroll 1
        for (int i = 0; i < 27; i++) {
            if (lane < 27 && i <= lane) {
                orow[26 * i - (i * (i - 1)) / 2 + lane] = gstage[i * 33 + lane];
            }
        }
    }
}

extern "C" void kernel_launch(void* const* d_in, const int* in_sizes, int n_in,
                              void* d_out, int out_size)
{
    const float4* dense4  = (const float4*)d_in[0];
    const float4* sparse4 = (const float4*)d_in[1];
    float*        out     = (float*)d_out;

    int B = in_sizes[0] / 128;
    int grid = (B + WPC - 1) / WPC;

    cudaFuncSetAttribute(dot_interact_mma,
                         cudaFuncAttributeMaxDynamicSharedMemorySize, SMEMTOT);
    dot_interact_mma<<<grid, THREADS, SMEMTOT>>>(dense4, sparse4, out, B);
    (void)n_in; (void)out_size;
}

// round 11
// speedup vs baseline: 1.3635x; 1.2268x over previous
#include <cuda_runtime.h>
#include <cuda_bf16.h>
#include <cstdint>

// DotInteract: out[b] = concat(dense[b] (128), triu(C C^T) (378)),
// C = [dense[b]; sparse[b,0..25]] (27x128 fp32). B = 32768, OUTW = 506.
//
// One warp per sample, Gram via mma.sync.m16n8k16 bf16.
// fp32 = bf16 hi + lo; D = hi.hi^T + hi.lo^T + lo.hi^T (err ~3e-6).
// R11 = R10 (single-buffer cp.async raw staging, 6 CTAs/SM) plus:
//  - flat-triu epilogue: fragments scatter straight into a flat 378-float
//    stage; output written with 6 coalesced LDS.64+STG.64 (was 27+27 narrow)
//  - LDSM addresses hoisted out of the chunk loop (chunk-invariant)

#define THREADS 128
#define WPC     4                    // warps = samples per CTA
#define OUTW    506
#define TSTRIDE 80                   // tile row bytes (conflict-free LDSM)
#define TBYTES  (32 * TSTRIDE)       // 2560 per split tile
#define TILES   (2 * TBYTES)         // hi + lo = 5120 (also epilogue stage)
#define RAWSTR  144                  // raw row stride bytes (36 floats)
#define RAWB    (27 * RAWSTR)        // 3888: one raw chunk buffer
#define WSTR    (TILES + RAWB)       // 9008 per warp
#define SMEMTOT (WPC * WSTR)         // 36032 per CTA -> 6 CTAs/SM

__device__ __forceinline__ uint32_t smem_u32(const void* p) {
    uint32_t a;
    asm("{ .reg .u64 t; cvta.to.shared.u64 t, %1; cvt.u32.u64 %0, t; }" : "=r"(a) : "l"(p));
    return a;
}
__device__ __forceinline__ uint32_t pack_bf16x2(float lo, float hi) {
    uint32_t r;  // d = { cvt(hi)=upper16 | cvt(lo)=lower16 }
    asm("cvt.rn.bf16x2.f32 %0, %1, %2;" : "=r"(r) : "f"(hi), "f"(lo));
    return r;
}
__device__ __forceinline__ float bf_lo(uint32_t p) { return __uint_as_float(p << 16); }
__device__ __forceinline__ float bf_hi(uint32_t p) { return __uint_as_float(p & 0xFFFF0000u); }

__device__ __forceinline__ void cpasync16(uint32_t dst, const float4* src, bool pred) {
    asm volatile("{\n\t.reg .pred p;\n\tsetp.ne.u32 p, %2, 0;\n\t"
                 "@p cp.async.cg.shared.global [%0], [%1], 16;\n\t}"
                 :: "r"(dst), "l"(src), "r"((uint32_t)pred));
}
#define CP_COMMIT() asm volatile("cp.async.commit_group;" ::: "memory")
#define CP_WAIT0()  asm volatile("cp.async.wait_group 0;"  ::: "memory")

__device__ __forceinline__ void ldsm4(uint32_t* r, uint32_t addr) {
    asm volatile("ldmatrix.sync.aligned.m8n8.x4.shared.b16 {%0,%1,%2,%3}, [%4];"
                 : "=r"(r[0]), "=r"(r[1]), "=r"(r[2]), "=r"(r[3]) : "r"(addr));
}
__device__ __forceinline__ void mma16816(float* d, const uint32_t* a,
                                         uint32_t b0, uint32_t b1) {
    asm volatile("mma.sync.aligned.m16n8k16.row.col.f32.bf16.bf16.f32 "
                 "{%0,%1,%2,%3}, {%4,%5,%6,%7}, {%8,%9}, {%0,%1,%2,%3};"
                 : "+f"(d[0]), "+f"(d[1]), "+f"(d[2]), "+f"(d[3])
                 : "r"(a[0]), "r"(a[1]), "r"(a[2]), "r"(a[3]), "r"(b0), "r"(b1));
}
__device__ __forceinline__ void do_pair(float* c00, float* c01, float* c02, float* c03,
                                        float* c12, float* c13,
                                        const uint32_t* S0, const uint32_t* S1,
                                        const uint32_t* T0, const uint32_t* T1) {
    mma16816(c00, S0, T0[0], T0[2]);
    mma16816(c01, S0, T0[1], T0[3]);
    mma16816(c02, S0, T1[0], T1[2]);
    mma16816(c03, S0, T1[1], T1[3]);
    mma16816(c12, S1, T1[0], T1[2]);
    mma16816(c13, S1, T1[1], T1[3]);
}

extern __shared__ char smem[];

__global__ void __launch_bounds__(THREADS, 6)
dot_interact_mma(const float4* __restrict__ dense4,
                 const float4* __restrict__ sparse4,
                 float* __restrict__ out, int B)
{
    const int warp = threadIdx.x >> 5;
    const int lane = threadIdx.x & 31;
    const int b    = blockIdx.x * WPC + warp;
    if (b >= B) return;

    const uint32_t hiBase  = smem_u32(smem) + warp * WSTR;
    const uint32_t loBase  = hiBase + TBYTES;
    const uint32_t rawBase = hiBase + TILES;

    // ---- zero pad tile rows 27..31 (once) ----
    #pragma unroll
    for (int it = 0; it < 3; it++) {
        int idx = it * 32 + lane;                  // need < 80
        if (idx < 80) {
            int t   = idx >= 40;
            int rem = idx - t * 40;
            uint32_t ad = (t ? loBase : hiBase) + (27 + (rem >> 3)) * TSTRIDE + (rem & 7) * 8;
            asm volatile("st.shared.v2.b32 [%0], {%1, %1};" :: "r"(ad), "r"(0u));
        }
    }

    // ---- affine plan: it = 0..6, row r = r0 + 4*it, c4 = lane&7 ----
    const int r0 = lane >> 3;                      // 0..3
    const int c4 = lane & 7;
    const bool dlane   = (r0 == 0);                // it==0 reads dense
    const bool tail_ok = (lane < 24);              // it==6 rows 24..26 only
    const float4* dptr = dense4 + (long long)b * 32 + c4;
    const float4* sptr = sparse4 + ((long long)b * 26 + (r0 - 1)) * 32 + c4;
    const uint32_t rOff0 = (uint32_t)(r0 * RAWSTR + c4 * 16);
    const uint32_t sOff0 = (uint32_t)(r0 * TSTRIDE + c4 * 8);

    // ---- hoisted chunk-invariant LDSM addresses (8 regs) ----
    const int lrow = ((lane >> 3) & 1) * 8 + (lane & 7);
    const int lu   = lane >> 4;
    uint32_t lA[8];
    #pragma unroll
    for (int ks = 0; ks < 2; ks++) {
        uint32_t off0 = (uint32_t)(lrow * TSTRIDE + (2 * ks + lu) * 16);
        lA[4 * ks + 0] = hiBase + off0;
        lA[4 * ks + 1] = hiBase + off0 + 16 * TSTRIDE;
        lA[4 * ks + 2] = loBase + off0;
        lA[4 * ks + 3] = loBase + off0 + 16 * TSTRIDE;
    }

    float c00[4] = {0,0,0,0}, c01[4] = {0,0,0,0}, c02[4] = {0,0,0,0};
    float c03[4] = {0,0,0,0}, c12[4] = {0,0,0,0}, c13[4] = {0,0,0,0};

    float2* out2 = reinterpret_cast<float2*>(out) + (long long)b * (OUTW / 2);

    // ---- prologue: async-load chunk 0 ----
    #pragma unroll
    for (int it = 0; it < 7; it++) {
        bool pred = (it < 6) | tail_ok;
        const float4* src = (it == 0 && dlane) ? dptr : (sptr + it * 128);
        cpasync16(rawBase + rOff0 + it * (4 * RAWSTR), src, pred);
    }
    CP_COMMIT();

    #pragma unroll
    for (int kc = 0; kc < 4; kc++) {
        CP_WAIT0();     // own lane's slots now valid (lane reads only own slots)

        // ---- convert: LDS own raw slots -> split bf16 hi/lo -> STS tiles ----
        #pragma unroll
        for (int it = 0; it < 7; it++) {
            if (it == 6 && !tail_ok) break;
            float4 v;
            asm volatile("ld.shared.v4.b32 {%0,%1,%2,%3}, [%4];"
                         : "=f"(v.x), "=f"(v.y), "=f"(v.z), "=f"(v.w)
                         : "r"(rawBase + rOff0 + it * (4 * RAWSTR)));
            uint32_t h01 = pack_bf16x2(v.x, v.y);
            uint32_t h23 = pack_bf16x2(v.z, v.w);
            uint32_t l01 = pack_bf16x2(v.x - bf_lo(h01), v.y - bf_hi(h01));
            uint32_t l23 = pack_bf16x2(v.z - bf_lo(h23), v.w - bf_hi(h23));
            uint32_t so = sOff0 + it * (4 * TSTRIDE);
            asm volatile("st.shared.v2.b32 [%0], {%1, %2};"
                         :: "r"(hiBase + so), "r"(h01), "r"(h23));
            asm volatile("st.shared.v2.b32 [%0], {%1, %2};"
                         :: "r"(loBase + so), "r"(l01), "r"(l23));
            if (it == 0 && dlane) {                // lanes 0..7: dense passthrough
                out2[kc * 16 + lane * 2]     = make_float2(v.x, v.y);
                out2[kc * 16 + lane * 2 + 1] = make_float2(v.z, v.w);
            }
        }

        // ---- refill same buffer with chunk kc+1 (per-lane WAR safe) ----
        if (kc < 3) {
            #pragma unroll
            for (int it = 0; it < 7; it++) {
                bool pred = (it < 6) | tail_ok;
                const float4* src = (it == 0 && dlane) ? (dptr + (kc + 1) * 8)
                                                       : (sptr + (kc + 1) * 8 + it * 128);
                cpasync16(rawBase + rOff0 + it * (4 * RAWSTR), src, pred);
            }
            CP_COMMIT();
        }
        __syncwarp();   // STS tiles visible to whole warp before LDSM

        // ---- compute: 2 k-steps x (4 LDSM.x4 + 18 HMMA); loads overlap this ----
        #pragma unroll
        for (int ks = 0; ks < 2; ks++) {
            uint32_t H0[4], H1[4], L0[4], L1[4];
            ldsm4(H0, lA[4 * ks + 0]);
            ldsm4(H1, lA[4 * ks + 1]);
            ldsm4(L0, lA[4 * ks + 2]);
            ldsm4(L1, lA[4 * ks + 3]);
            do_pair(c00, c01, c02, c03, c12, c13, H0, H1, H0, H1);  // hi.hi
            do_pair(c00, c01, c02, c03, c12, c13, H0, H1, L0, L1);  // hi.lo
            do_pair(c00, c01, c02, c03, c12, c13, L0, L1, H0, H1);  // lo.hi
        }
        __syncwarp();   // WAR before tile restaging
    }

    // ---- epilogue: fragments -> FLAT triu stage (378 floats) ----
    float* stage = reinterpret_cast<float*>(smem + warp * WSTR);   // reuse tiles
    {
        const int fr = lane >> 2;                 // 0..7
        const int fc = 2 * (lane & 3);            // 0,2,4,6
        float* t[6] = {c00, c01, c02, c03, c12, c13};
        const int mi[6] = {0, 0, 0, 0, 16, 16};
        const int nj[6] = {0, 8, 16, 24, 16, 24};
        #pragma unroll
        for (int q = 0; q < 6; q++) {
            int i0 = mi[q] + fr, j0 = nj[q] + fc;
            #pragma unroll
            for (int e = 0; e < 4; e++) {
                int i = i0 + (e >> 1) * 8;
                int j = j0 + (e & 1);
                if (j >= i && j <= 26) {
                    stage[26 * i - ((i * (i - 1)) >> 1) + j] = t[q][e];
                }
            }
        }
    }
    __syncwarp();

    {   // coalesced triu write: 189 float2 per sample
        float2* st2  = reinterpret_cast<float2*>(stage);
        float2* orow = reinterpret_cast<float2*>(out + (long long)b * OUTW + 128);
        #pragma unroll
        for (int t = 0; t < 6; t++) {
            int idx = t * 32 + lane;
            if (idx < 189) orow[idx] = st2[idx];
        }
    }
}

extern "C" void kernel_launch(void* const* d_in, const int* in_sizes, int n_in,
                              void* d_out, int out_size)
{
    const float4* dense4  = (const float4*)d_in[0];
    const float4* sparse4 = (const float4*)d_in[1];
    float*        out     = (float*)d_out;

    int B = in_sizes[0] / 128;
    int grid = (B + WPC - 1) / WPC;

    cudaFuncSetAttribute(dot_interact_mma,
                         cudaFuncAttributeMaxDynamicSharedMemorySize, SMEMTOT);
    dot_interact_mma<<<grid, THREADS, SMEMTOT>>>(dense4, sparse4, out, B);
    (void)n_in; (void)out_size;
}

// round 12
// speedup vs baseline: 1.4258x; 1.0457x over previous
#include <cuda_runtime.h>
#include <cuda_bf16.h>
#include <cstdint>

// DotInteract: out[b] = concat(dense[b] (128), triu(C C^T) (378)),
// C = [dense[b]; sparse[b,0..25]] (27x128 fp32). B = 32768, OUTW = 506.
//
// One warp per sample, Gram via mma.sync.m16n8k16 bf16.
// fp32 = bf16 hi + lo; D = hi.hi^T + hi.lo^T + lo.hi^T (err ~3e-6).
// R12 = R11 squeezed to 7 CTAs/SM:
//  - RAWSTR 128 (pad unneeded: every 8-lane wavefront covers distinct banks)
//  - tiles shrunk to 28 rows; LDSM rows 28-31 read garbage that provably
//    lands only in discarded Gram rows/cols >= 27
//  - LDSM addresses recomputed per chunk; __launch_bounds__(128,7) (72 regs)

#define THREADS 128
#define WPC     4                    // warps = samples per CTA
#define OUTW    506
#define TSTRIDE 80                   // tile row bytes (conflict-free LDSM)
#define TBYTES  (28 * TSTRIDE)       // 2240 per split tile (27 rows + 1 slack)
#define TILES   (2 * TBYTES)         // hi + lo = 4480 (also epilogue stage)
#define RAWSTR  128                  // raw row stride bytes (32 floats)
#define RAWB    (27 * RAWSTR)        // 3456: one raw chunk buffer
#define WSTR    (TILES + RAWB)       // 7936 per warp
#define SMEMTOT (WPC * WSTR)         // 31744 per CTA -> 7 CTAs/SM

__device__ __forceinline__ uint32_t smem_u32(const void* p) {
    uint32_t a;
    asm("{ .reg .u64 t; cvta.to.shared.u64 t, %1; cvt.u32.u64 %0, t; }" : "=r"(a) : "l"(p));
    return a;
}
__device__ __forceinline__ uint32_t pack_bf16x2(float lo, float hi) {
    uint32_t r;  // d = { cvt(hi)=upper16 | cvt(lo)=lower16 }
    asm("cvt.rn.bf16x2.f32 %0, %1, %2;" : "=r"(r) : "f"(hi), "f"(lo));
    return r;
}
__device__ __forceinline__ float bf_lo(uint32_t p) { return __uint_as_float(p << 16); }
__device__ __forceinline__ float bf_hi(uint32_t p) { return __uint_as_float(p & 0xFFFF0000u); }

__device__ __forceinline__ void cpasync16(uint32_t dst, const float4* src, bool pred) {
    asm volatile("{\n\t.reg .pred p;\n\tsetp.ne.u32 p, %2, 0;\n\t"
                 "@p cp.async.cg.shared.global [%0], [%1], 16;\n\t}"
                 :: "r"(dst), "l"(src), "r"((uint32_t)pred));
}
#define CP_COMMIT() asm volatile("cp.async.commit_group;" ::: "memory")
#define CP_WAIT0()  asm volatile("cp.async.wait_group 0;"  ::: "memory")

__device__ __forceinline__ void ldsm4(uint32_t* r, uint32_t addr) {
    asm volatile("ldmatrix.sync.aligned.m8n8.x4.shared.b16 {%0,%1,%2,%3}, [%4];"
                 : "=r"(r[0]), "=r"(r[1]), "=r"(r[2]), "=r"(r[3]) : "r"(addr));
}
__device__ __forceinline__ void mma16816(float* d, const uint32_t* a,
                                         uint32_t b0, uint32_t b1) {
    asm volatile("mma.sync.aligned.m16n8k16.row.col.f32.bf16.bf16.f32 "
                 "{%0,%1,%2,%3}, {%4,%5,%6,%7}, {%8,%9}, {%0,%1,%2,%3};"
                 : "+f"(d[0]), "+f"(d[1]), "+f"(d[2]), "+f"(d[3])
                 : "r"(a[0]), "r"(a[1]), "r"(a[2]), "r"(a[3]), "r"(b0), "r"(b1));
}
__device__ __forceinline__ void do_pair(float* c00, float* c01, float* c02, float* c03,
                                        float* c12, float* c13,
                                        const uint32_t* S0, const uint32_t* S1,
                                        const uint32_t* T0, const uint32_t* T1) {
    mma16816(c00, S0, T0[0], T0[2]);
    mma16816(c01, S0, T0[1], T0[3]);
    mma16816(c02, S0, T1[0], T1[2]);
    mma16816(c03, S0, T1[1], T1[3]);
    mma16816(c12, S1, T1[0], T1[2]);
    mma16816(c13, S1, T1[1], T1[3]);
}

extern __shared__ char smem[];

__global__ void __launch_bounds__(THREADS, 7)
dot_interact_mma(const float4* __restrict__ dense4,
                 const float4* __restrict__ sparse4,
                 float* __restrict__ out, int B)
{
    const int warp = threadIdx.x >> 5;
    const int lane = threadIdx.x & 31;
    const int b    = blockIdx.x * WPC + warp;
    if (b >= B) return;

    const uint32_t hiBase  = smem_u32(smem) + warp * WSTR;
    const uint32_t loBase  = hiBase + TBYTES;
    const uint32_t rawBase = hiBase + TILES;

    // ---- affine plan: it = 0..6, row r = r0 + 4*it, c4 = lane&7 ----
    const int r0 = lane >> 3;                      // 0..3
    const int c4 = lane & 7;
    const bool dlane   = (r0 == 0);                // it==0 reads dense
    const bool tail_ok = (lane < 24);              // it==6 rows 24..26 only
    const float4* dptr = dense4 + (long long)b * 32 + c4;
    const float4* sptr = sparse4 + ((long long)b * 26 + (r0 - 1)) * 32 + c4;
    const uint32_t rOff0 = (uint32_t)(r0 * RAWSTR + c4 * 16);
    const uint32_t sOff0 = (uint32_t)(r0 * TSTRIDE + c4 * 8);

    const int lrow = ((lane >> 3) & 1) * 8 + (lane & 7);
    const int lu   = lane >> 4;
    const uint32_t lBase = (uint32_t)(lrow * TSTRIDE + lu * 16);

    float c00[4] = {0,0,0,0}, c01[4] = {0,0,0,0}, c02[4] = {0,0,0,0};
    float c03[4] = {0,0,0,0}, c12[4] = {0,0,0,0}, c13[4] = {0,0,0,0};

    float2* out2 = reinterpret_cast<float2*>(out) + (long long)b * (OUTW / 2);

    // ---- prologue: async-load chunk 0 ----
    #pragma unroll
    for (int it = 0; it < 7; it++) {
        bool pred = (it < 6) | tail_ok;
        const float4* src = (it == 0 && dlane) ? dptr : (sptr + it * 128);
        cpasync16(rawBase + rOff0 + it * (4 * RAWSTR), src, pred);
    }
    CP_COMMIT();

    #pragma unroll
    for (int kc = 0; kc < 4; kc++) {
        CP_WAIT0();     // own lane's slots now valid (lane reads only own slots)

        // ---- convert: LDS own raw slots -> split bf16 hi/lo -> STS tiles ----
        #pragma unroll
        for (int it = 0; it < 7; it++) {
            if (it == 6 && !tail_ok) break;
            float4 v;
            asm volatile("ld.shared.v4.b32 {%0,%1,%2,%3}, [%4];"
                         : "=f"(v.x), "=f"(v.y), "=f"(v.z), "=f"(v.w)
                         : "r"(rawBase + rOff0 + it * (4 * RAWSTR)));
            uint32_t h01 = pack_bf16x2(v.x, v.y);
            uint32_t h23 = pack_bf16x2(v.z, v.w);
            uint32_t l01 = pack_bf16x2(v.x - bf_lo(h01), v.y - bf_hi(h01));
            uint32_t l23 = pack_bf16x2(v.z - bf_lo(h23), v.w - bf_hi(h23));
            uint32_t so = sOff0 + it * (4 * TSTRIDE);
            asm volatile("st.shared.v2.b32 [%0], {%1, %2};"
                         :: "r"(hiBase + so), "r"(h01), "r"(h23));
            asm volatile("st.shared.v2.b32 [%0], {%1, %2};"
                         :: "r"(loBase + so), "r"(l01), "r"(l23));
            if (it == 0 && dlane) {                // lanes 0..7: dense passthrough
                out2[kc * 16 + lane * 2]     = make_float2(v.x, v.y);
                out2[kc * 16 + lane * 2 + 1] = make_float2(v.z, v.w);
            }
        }

        // ---- refill same buffer with chunk kc+1 (per-lane WAR safe) ----
        if (kc < 3) {
            #pragma unroll
            for (int it = 0; it < 7; it++) {
                bool pred = (it < 6) | tail_ok;
                const float4* src = (it == 0 && dlane) ? (dptr + (kc + 1) * 8)
                                                       : (sptr + (kc + 1) * 8 + it * 128);
                cpasync16(rawBase + rOff0 + it * (4 * RAWSTR), src, pred);
            }
            CP_COMMIT();
        }
        __syncwarp();   // STS tiles visible to whole warp before LDSM

        // ---- compute: 2 k-steps x (4 LDSM.x4 + 18 HMMA); loads overlap this ----
        // Rows 27-31 of each LDSM window are garbage; they only feed Gram
        // rows/cols >= 27, which the epilogue predicate discards.
        #pragma unroll
        for (int ks = 0; ks < 2; ks++) {
            uint32_t off0 = lBase + ks * 32;
            uint32_t H0[4], H1[4], L0[4], L1[4];
            ldsm4(H0, hiBase + off0);
            ldsm4(H1, hiBase + off0 + 16 * TSTRIDE);
            ldsm4(L0, loBase + off0);
            ldsm4(L1, loBase + off0 + 16 * TSTRIDE);
            do_pair(c00, c01, c02, c03, c12, c13, H0, H1, H0, H1);  // hi.hi
            do_pair(c00, c01, c02, c03, c12, c13, H0, H1, L0, L1);  // hi.lo
            do_pair(c00, c01, c02, c03, c12, c13, L0, L1, H0, H1);  // lo.hi
        }
        __syncwarp();   // WAR before tile restaging
    }

    // ---- epilogue: fragments -> FLAT triu stage (378 floats) ----
    float* stage = reinterpret_cast<float*>(smem + warp * WSTR);   // reuse tiles
    {
        const int fr = lane >> 2;                 // 0..7
        const int fc = 2 * (lane & 3);            // 0,2,4,6
        float* t[6] = {c00, c01, c02, c03, c12, c13};
        const int mi[6] = {0, 0, 0, 0, 16, 16};
        const int nj[6] = {0, 8, 16, 24, 16, 24};
        #pragma unroll
        for (int q = 0; q < 6; q++) {
            int i0 = mi[q] + fr, j0 = nj[q] + fc;
            #pragma unroll
            for (int e = 0; e < 4; e++) {
                int i = i0 + (e >> 1) * 8;
                int j = j0 + (e & 1);
                if (j >= i && j <= 26) {
                    stage[26 * i - ((i * (i - 1)) >> 1) + j] = t[q][e];
                }
            }
        }
    }
    __syncwarp();

    {   // coalesced triu write: 189 float2 per sample
        float2* st2  = reinterpret_cast<float2*>(stage);
        float2* orow = reinterpret_cast<float2*>(out + (long long)b * OUTW + 128);
        #pragma unroll
        for (int t = 0; t < 6; t++) {
            int idx = t * 32 + lane;
            if (idx < 189) orow[idx] = st2[idx];
        }
    }
}

extern "C" void kernel_launch(void* const* d_in, const int* in_sizes, int n_in,
                              void* d_out, int out_size)
{
    const float4* dense4  = (const float4*)d_in[0];
    const float4* sparse4 = (const float4*)d_in[1];
    float*        out     = (float*)d_out;

    int B = in_sizes[0] / 128;
    int grid = (B + WPC - 1) / WPC;

    cudaFuncSetAttribute(dot_interact_mma,
                         cudaFuncAttributeMaxDynamicSharedMemorySize, SMEMTOT);
    dot_interact_mma<<<grid, THREADS, SMEMTOT>>>(dense4, sparse4, out, B);
    (void)n_in; (void)out_size;
}

// round 13
// speedup vs baseline: 1.4992x; 1.0515x over previous
#include <cuda_runtime.h>
#include <cuda_bf16.h>
#include <cstdint>

// DotInteract: out[b] = concat(dense[b] (128), triu(C C^T) (378)),
// C = [dense[b]; sparse[b,0..25]] (27x128 fp32). B = 32768, OUTW = 506.
//
// One warp per sample, Gram via mma.sync.m16n8k16 bf16 (hi+lo split, 3 passes).
// R13: MMA fragments are built DIRECTLY from the cp.async'd raw fp32 buffer
// with LDS.64 + in-register bf16 split. The A-frag registers double as the
// B-frags (C.C^T symmetry: a0/a2 of row-block t == b0/b1 of col-tile t), so
// the bf16 tiles, STS and LDSM of R12 are deleted: smem wavefronts per chunk
// drop 116 -> 60. RAWSTR=160 makes LDS.64 (8r+2c mod 32) conflict-free.

#define THREADS 128
#define WPC     4                    // warps = samples per CTA
#define OUTW    506
#define RAWSTR  160                  // raw row stride bytes (40 floats)
#define WSTR    (32 * RAWSTR)        // 5120: rows 0..31 legal (27..31 garbage)
#define SMEMTOT (WPC * WSTR)         // 20480 per CTA -> 7 CTAs/SM

__device__ __forceinline__ uint32_t smem_u32(const void* p) {
    uint32_t a;
    asm("{ .reg .u64 t; cvta.to.shared.u64 t, %1; cvt.u32.u64 %0, t; }" : "=r"(a) : "l"(p));
    return a;
}
__device__ __forceinline__ uint32_t pack_bf16x2(float lo, float hi) {
    uint32_t r;  // d = { cvt(hi)=upper16 | cvt(lo)=lower16 }
    asm("cvt.rn.bf16x2.f32 %0, %1, %2;" : "=r"(r) : "f"(hi), "f"(lo));
    return r;
}
__device__ __forceinline__ float bf_lo(uint32_t p) { return __uint_as_float(p << 16); }
__device__ __forceinline__ float bf_hi(uint32_t p) { return __uint_as_float(p & 0xFFFF0000u); }

__device__ __forceinline__ void cpasync16(uint32_t dst, const float4* src, bool pred) {
    asm volatile("{\n\t.reg .pred p;\n\tsetp.ne.u32 p, %2, 0;\n\t"
                 "@p cp.async.cg.shared.global [%0], [%1], 16;\n\t}"
                 :: "r"(dst), "l"(src), "r"((uint32_t)pred));
}
#define CP_COMMIT() asm volatile("cp.async.commit_group;" ::: "memory")
#define CP_WAIT0()  asm volatile("cp.async.wait_group 0;"  ::: "memory")

// load 2 fp32 from smem, split into bf16x2 hi and lo regs
__device__ __forceinline__ void ld2_split(uint32_t addr, uint32_t& h, uint32_t& l) {
    float f0, f1;
    asm volatile("ld.shared.v2.f32 {%0, %1}, [%2];" : "=f"(f0), "=f"(f1) : "r"(addr));
    h = pack_bf16x2(f0, f1);
    l = pack_bf16x2(f0 - bf_lo(h), f1 - bf_hi(h));
}

__device__ __forceinline__ void mma16816(float* d, const uint32_t* a,
                                         uint32_t b0, uint32_t b1) {
    asm volatile("mma.sync.aligned.m16n8k16.row.col.f32.bf16.bf16.f32 "
                 "{%0,%1,%2,%3}, {%4,%5,%6,%7}, {%8,%9}, {%0,%1,%2,%3};"
                 : "+f"(d[0]), "+f"(d[1]), "+f"(d[2]), "+f"(d[3])
                 : "r"(a[0]), "r"(a[1]), "r"(a[2]), "r"(a[3]), "r"(b0), "r"(b1));
}
__device__ __forceinline__ void do_pair(float* c00, float* c01, float* c02, float* c03,
                                        float* c12, float* c13,
                                        const uint32_t* S0, const uint32_t* S1,
                                        const uint32_t* T0, const uint32_t* T1) {
    mma16816(c00, S0, T0[0], T0[2]);
    mma16816(c01, S0, T0[1], T0[3]);
    mma16816(c02, S0, T1[0], T1[2]);
    mma16816(c03, S0, T1[1], T1[3]);
    mma16816(c12, S1, T1[0], T1[2]);
    mma16816(c13, S1, T1[1], T1[3]);
}

extern __shared__ char smem[];

__global__ void __launch_bounds__(THREADS, 7)
dot_interact_mma(const float4* __restrict__ dense4,
                 const float4* __restrict__ sparse4,
                 float* __restrict__ out, int B)
{
    const int warp = threadIdx.x >> 5;
    const int lane = threadIdx.x & 31;
    const int b    = blockIdx.x * WPC + warp;
    if (b >= B) return;

    const uint32_t rawBase = smem_u32(smem) + warp * WSTR;

    // ---- staging plan (cp.async): it = 0..6, row r0 + 4*it, c4 = lane&7 ----
    const int r0 = lane >> 3;                      // 0..3
    const int c4 = lane & 7;
    const bool dlane   = (r0 == 0);                // it==0 reads dense
    const bool tail_ok = (lane < 24);              // it==6 rows 24..26 only
    const float4* dptr = dense4 + (long long)b * 32 + c4;
    const float4* sptr = sparse4 + ((long long)b * 26 + (r0 - 1)) * 32 + c4;
    const uint32_t wOff0 = (uint32_t)(r0 * RAWSTR + c4 * 16);

    // ---- fragment plan: r = lane>>2 (0..7), c = lane&3 ----
    const int fr = lane >> 2;
    const int fc = lane & 3;
    const uint32_t fOff = rawBase + (uint32_t)(fr * RAWSTR + fc * 8);  // (row fr, col 2c)

    float c00[4] = {0,0,0,0}, c01[4] = {0,0,0,0}, c02[4] = {0,0,0,0};
    float c03[4] = {0,0,0,0}, c12[4] = {0,0,0,0}, c13[4] = {0,0,0,0};

    float2* out2 = reinterpret_cast<float2*>(out) + (long long)b * (OUTW / 2);

    // ---- prologue: async-load chunk 0 ----
    #pragma unroll
    for (int it = 0; it < 7; it++) {
        bool pred = (it < 6) | tail_ok;
        const float4* src = (it == 0 && dlane) ? dptr : (sptr + it * 128);
        cpasync16(rawBase + wOff0 + it * (4 * RAWSTR), src, pred);
    }
    CP_COMMIT();

    #pragma unroll
    for (int kc = 0; kc < 4; kc++) {
        CP_WAIT0();
        __syncwarp();    // all lanes' chunk-kc data visible (cross-lane reads)

        // ---- build hi/lo fragments for both k-steps (32 regs) ----
        // S0 = rows fr, fr+8; S1 = rows fr+16, fr+24; a2/a3 at col +8.
        uint32_t S0h[2][4], S0l[2][4], S1h[2][4], S1l[2][4];
        #pragma unroll
        for (int ks = 0; ks < 2; ks++) {
            uint32_t base = fOff + ks * 64;                       // k-window 16ks
            ld2_split(base,                          S0h[ks][0], S0l[ks][0]);
            ld2_split(base + 8 * RAWSTR,             S0h[ks][1], S0l[ks][1]);
            ld2_split(base + 32,                     S0h[ks][2], S0l[ks][2]);
            ld2_split(base + 8 * RAWSTR + 32,        S0h[ks][3], S0l[ks][3]);
            ld2_split(base + 16 * RAWSTR,            S1h[ks][0], S1l[ks][0]);
            ld2_split(base + 24 * RAWSTR,            S1h[ks][1], S1l[ks][1]);
            ld2_split(base + 16 * RAWSTR + 32,       S1h[ks][2], S1l[ks][2]);
            ld2_split(base + 24 * RAWSTR + 32,       S1h[ks][3], S1l[ks][3]);
        }

        // ---- dense passthrough: row 0 = dense[b][32kc..] (lanes 0..15) ----
        if (lane < 16) {
            float2 dv;
            asm volatile("ld.shared.v2.f32 {%0, %1}, [%2];"
                         : "=f"(dv.x), "=f"(dv.y) : "r"(rawBase + lane * 8));
            out2[kc * 16 + lane] = dv;
        }
        __syncwarp();    // all raw reads done before refill overwrites

        // ---- refill same buffer with chunk kc+1 ----
        if (kc < 3) {
            #pragma unroll
            for (int it = 0; it < 7; it++) {
                bool pred = (it < 6) | tail_ok;
                const float4* src = (it == 0 && dlane) ? (dptr + (kc + 1) * 8)
                                                       : (sptr + (kc + 1) * 8 + it * 128);
                cpasync16(rawBase + wOff0 + it * (4 * RAWSTR), src, pred);
            }
            CP_COMMIT();
        }

        // ---- MMAs (register-only; overlap the in-flight refill) ----
        #pragma unroll
        for (int ks = 0; ks < 2; ks++) {
            do_pair(c00, c01, c02, c03, c12, c13, S0h[ks], S1h[ks], S0h[ks], S1h[ks]);
            do_pair(c00, c01, c02, c03, c12, c13, S0h[ks], S1h[ks], S0l[ks], S1l[ks]);
            do_pair(c00, c01, c02, c03, c12, c13, S0l[ks], S1l[ks], S0h[ks], S1h[ks]);
        }
    }

    // ---- epilogue: fragments -> FLAT triu stage (378 floats, reuse raw) ----
    float* stage = reinterpret_cast<float*>(smem + warp * WSTR);
    {
        const int er = lane >> 2;                 // 0..7
        const int ec = 2 * (lane & 3);            // 0,2,4,6
        float* t[6] = {c00, c01, c02, c03, c12, c13};
        const int mi[6] = {0, 0, 0, 0, 16, 16};
        const int nj[6] = {0, 8, 16, 24, 16, 24};
        #pragma unroll
        for (int q = 0; q < 6; q++) {
            int i0 = mi[q] + er, j0 = nj[q] + ec;
            #pragma unroll
            for (int e = 0; e < 4; e++) {
                int i = i0 + (e >> 1) * 8;
                int j = j0 + (e & 1);
                if (j >= i && j <= 26) {
                    stage[26 * i - ((i * (i - 1)) >> 1) + j] = t[q][e];
                }
            }
        }
    }
    __syncwarp();

    {   // coalesced triu write: 189 float2 per sample
        float2* st2  = reinterpret_cast<float2*>(stage);
        float2* orow = reinterpret_cast<float2*>(out + (long long)b * OUTW + 128);
        #pragma unroll
        for (int t = 0; t < 6; t++) {
            int idx = t * 32 + lane;
            if (idx < 189) orow[idx] = st2[idx];
        }
    }
}

extern "C" void kernel_launch(void* const* d_in, const int* in_sizes, int n_in,
                              void* d_out, int out_size)
{
    const float4* dense4  = (const float4*)d_in[0];
    const float4* sparse4 = (const float4*)d_in[1];
    float*        out     = (float*)d_out;

    int B = in_sizes[0] / 128;
    int grid = (B + WPC - 1) / WPC;

    cudaFuncSetAttribute(dot_interact_mma,
                         cudaFuncAttributeMaxDynamicSharedMemorySize, SMEMTOT);
    dot_interact_mma<<<grid, THREADS, SMEMTOT>>>(dense4, sparse4, out, B);
    (void)n_in; (void)out_size;
}

// round 14
// speedup vs baseline: 1.4998x; 1.0004x over previous
#include <cuda_runtime.h>
#include <cuda_bf16.h>
#include <cstdint>

// DotInteract: out[b] = concat(dense[b] (128), triu(C C^T) (378)),
// C = [dense[b]; sparse[b,0..25]] (27x128 fp32). B = 32768, OUTW = 506.
//
// One warp per sample; Gram via mma.sync.m16n8k16 bf16, hi+lo split, 3 passes
// (err ~3e-6). Fragments built directly from a cp.async'd raw fp32 buffer via
// LDS.64 + in-register split; A-frag regs double as B-frags (C.C^T symmetry).
// R14: buffer widened to a 64-float k-block (27 x 288 B): pipeline waits and
// syncwarps halve (2 fills instead of 4), cp.async bursts double (MLP 14),
// 7 CTAs/SM retained (31104 B/CTA). Out-of-range frag rows clamp to row 26
// (garbage only reaches discarded Gram rows/cols >= 27).

#define THREADS 128
#define WPC     4                    // warps = samples per CTA
#define OUTW    506
#define RAWSTR  288                  // raw row stride bytes (72 words, = 8 mod 32 banks)
#define WSTR    (27 * RAWSTR)        // 7776 per warp
#define SMEMTOT (WPC * WSTR)         // 31104 per CTA -> 7 CTAs/SM

__device__ __forceinline__ uint32_t smem_u32(const void* p) {
    uint32_t a;
    asm("{ .reg .u64 t; cvta.to.shared.u64 t, %1; cvt.u32.u64 %0, t; }" : "=r"(a) : "l"(p));
    return a;
}
__device__ __forceinline__ uint32_t pack_bf16x2(float lo, float hi) {
    uint32_t r;  // d = { cvt(hi)=upper16 | cvt(lo)=lower16 }
    asm("cvt.rn.bf16x2.f32 %0, %1, %2;" : "=r"(r) : "f"(hi), "f"(lo));
    return r;
}
__device__ __forceinline__ float bf_lo(uint32_t p) { return __uint_as_float(p << 16); }
__device__ __forceinline__ float bf_hi(uint32_t p) { return __uint_as_float(p & 0xFFFF0000u); }

__device__ __forceinline__ void cpasync16(uint32_t dst, const float4* src, bool pred) {
    asm volatile("{\n\t.reg .pred p;\n\tsetp.ne.u32 p, %2, 0;\n\t"
                 "@p cp.async.cg.shared.global [%0], [%1], 16;\n\t}"
                 :: "r"(dst), "l"(src), "r"((uint32_t)pred));
}
#define CP_COMMIT() asm volatile("cp.async.commit_group;" ::: "memory")
#define CP_WAIT0()  asm volatile("cp.async.wait_group 0;"  ::: "memory")

// load 2 fp32 from smem, split into bf16x2 hi and lo regs
__device__ __forceinline__ void ld2_split(uint32_t addr, uint32_t& h, uint32_t& l) {
    float f0, f1;
    asm volatile("ld.shared.v2.f32 {%0, %1}, [%2];" : "=f"(f0), "=f"(f1) : "r"(addr));
    h = pack_bf16x2(f0, f1);
    l = pack_bf16x2(f0 - bf_lo(h), f1 - bf_hi(h));
}

__device__ __forceinline__ void mma16816(float* d, const uint32_t* a,
                                         uint32_t b0, uint32_t b1) {
    asm volatile("mma.sync.aligned.m16n8k16.row.col.f32.bf16.bf16.f32 "
                 "{%0,%1,%2,%3}, {%4,%5,%6,%7}, {%8,%9}, {%0,%1,%2,%3};"
                 : "+f"(d[0]), "+f"(d[1]), "+f"(d[2]), "+f"(d[3])
                 : "r"(a[0]), "r"(a[1]), "r"(a[2]), "r"(a[3]), "r"(b0), "r"(b1));
}
__device__ __forceinline__ void do_pair(float* c00, float* c01, float* c02, float* c03,
                                        float* c12, float* c13,
                                        const uint32_t* S0, const uint32_t* S1,
                                        const uint32_t* T0, const uint32_t* T1) {
    mma16816(c00, S0, T0[0], T0[2]);
    mma16816(c01, S0, T0[1], T0[3]);
    mma16816(c02, S0, T1[0], T1[2]);
    mma16816(c03, S0, T1[1], T1[3]);
    mma16816(c12, S1, T1[0], T1[2]);
    mma16816(c13, S1, T1[1], T1[3]);
}

extern __shared__ char smem[];

__global__ void __launch_bounds__(THREADS, 7)
dot_interact_mma(const float4* __restrict__ dense4,
                 const float4* __restrict__ sparse4,
                 float* __restrict__ out, int B)
{
    const int warp = threadIdx.x >> 5;
    const int lane = threadIdx.x & 31;
    const int b    = blockIdx.x * WPC + warp;
    if (b >= B) return;

    const uint32_t rawBase = smem_u32(smem) + warp * WSTR;

    // ---- staging plan: it = 0..13, row r = 2*it + r0l, col16 = lane&15 ----
    const int r0l = lane >> 4;                     // 0 or 1
    const int c16 = lane & 15;
    const bool dlane = (r0l == 0);                 // it==0, r0l==0 reads dense
    const float4* dptr = dense4 + (long long)b * 32 + c16;
    // row r>=1 -> sparse row r-1; valid for it>=1 (r0l=0) and it>=0 (r0l=1)
    const float4* sptr = sparse4 + ((long long)b * 26 + (r0l - 1)) * 32 + c16;
    const uint32_t wOff0 = (uint32_t)(r0l * RAWSTR + c16 * 16);

    // ---- fragment plan: fr = lane>>2 (0..7), fc = lane&3; rows clamped ----
    const int fr = lane >> 2;
    const int fc = lane & 3;
    const uint32_t A0 = rawBase + (uint32_t)(fr * RAWSTR + fc * 8);
    const uint32_t A1 = A0 + 8 * RAWSTR;
    const uint32_t A2 = A0 + 16 * RAWSTR;                        // rows 16..23
    const int r24 = (fr + 24 > 26) ? 26 : (fr + 24);             // clamp
    const uint32_t A3 = rawBase + (uint32_t)(r24 * RAWSTR + fc * 8);

    float c00[4] = {0,0,0,0}, c01[4] = {0,0,0,0}, c02[4] = {0,0,0,0};
    float c03[4] = {0,0,0,0}, c12[4] = {0,0,0,0}, c13[4] = {0,0,0,0};

    float2* out2 = reinterpret_cast<float2*>(out) + (long long)b * (OUTW / 2);

    // ---- prologue: async-load k-block 0 (cols 0..63) ----
    #pragma unroll
    for (int it = 0; it < 14; it++) {
        bool pred = (it < 13) | dlane;             // skip row 27 (it==13, r0l==1)
        const float4* src = (it == 0 && dlane) ? dptr : (sptr + it * 64);
        cpasync16(rawBase + wOff0 + it * (2 * RAWSTR), src, pred);
    }
    CP_COMMIT();

    #pragma unroll
    for (int kb = 0; kb < 2; kb++) {
        CP_WAIT0();
        __syncwarp();    // all lanes' fill visible (cross-lane reads)

        // ---- dense passthrough: row 0 = dense[b][64kb..64kb+63] ----
        {
            float2 dv;
            asm volatile("ld.shared.v2.f32 {%0, %1}, [%2];"
                         : "=f"(dv.x), "=f"(dv.y) : "r"(rawBase + lane * 8));
            out2[kb * 32 + lane] = dv;
        }

        // ---- 4 k-steps: build frags (8 LDS.64 + split) then MMA ----
        #pragma unroll
        for (int ks = 0; ks < 4; ks++) {
            uint32_t o = ks * 64;
            uint32_t S0h[4], S0l[4], S1h[4], S1l[4];
            ld2_split(A0 + o,      S0h[0], S0l[0]);
            ld2_split(A1 + o,      S0h[1], S0l[1]);
            ld2_split(A0 + o + 32, S0h[2], S0l[2]);
            ld2_split(A1 + o + 32, S0h[3], S0l[3]);
            ld2_split(A2 + o,      S1h[0], S1l[0]);
            ld2_split(A3 + o,      S1h[1], S1l[1]);
            ld2_split(A2 + o + 32, S1h[2], S1l[2]);
            ld2_split(A3 + o + 32, S1h[3], S1l[3]);

            if (ks == 3 && kb == 0) {
                // all reads of fill 0 done -> refill with k-block 1
                __syncwarp();
                #pragma unroll
                for (int it = 0; it < 14; it++) {
                    bool pred = (it < 13) | dlane;
                    const float4* src = (it == 0 && dlane) ? (dptr + 16)
                                                           : (sptr + it * 64 + 16);
                    cpasync16(rawBase + wOff0 + it * (2 * RAWSTR), src, pred);
                }
                CP_COMMIT();
            }

            do_pair(c00, c01, c02, c03, c12, c13, S0h, S1h, S0h, S1h);  // hi.hi
            do_pair(c00, c01, c02, c03, c12, c13, S0h, S1h, S0l, S1l);  // hi.lo
            do_pair(c00, c01, c02, c03, c12, c13, S0l, S1l, S0h, S1h);  // lo.hi
        }
    }

    // ---- epilogue: fragments -> FLAT triu stage (378 floats, reuse raw) ----
    // (last mma.sync warp-synchronizes all lanes; raw buffer is dead)
    float* stage = reinterpret_cast<float*>(smem + warp * WSTR);
    {
        const int er = lane >> 2;                 // 0..7
        const int ec = 2 * (lane & 3);            // 0,2,4,6
        float* t[6] = {c00, c01, c02, c03, c12, c13};
        const int mi[6] = {0, 0, 0, 0, 16, 16};
        const int nj[6] = {0, 8, 16, 24, 16, 24};
        #pragma unroll
        for (int q = 0; q < 6; q++) {
            int i0 = mi[q] + er, j0 = nj[q] + ec;
            #pragma unroll
            for (int e = 0; e < 4; e++) {
                int i = i0 + (e >> 1) * 8;
                int j = j0 + (e & 1);
                if (j >= i && j <= 26) {
                    stage[26 * i - ((i * (i - 1)) >> 1) + j] = t[q][e];
                }
            }
        }
    }
    __syncwarp();

    {   // coalesced triu write: 189 float2 per sample
        float2* st2  = reinterpret_cast<float2*>(stage);
        float2* orow = reinterpret_cast<float2*>(out + (long long)b * OUTW + 128);
        #pragma unroll
        for (int t = 0; t < 6; t++) {
            int idx = t * 32 + lane;
            if (idx < 189) orow[idx] = st2[idx];
        }
    }
}

extern "C" void kernel_launch(void* const* d_in, const int* in_sizes, int n_in,
                              void* d_out, int out_size)
{
    const float4* dense4  = (const float4*)d_in[0];
    const float4* sparse4 = (const float4*)d_in[1];
    float*        out     = (float*)d_out;

    int B = in_sizes[0] / 128;
    int grid = (B + WPC - 1) / WPC;

    cudaFuncSetAttribute(dot_interact_mma,
                         cudaFuncAttributeMaxDynamicSharedMemorySize, SMEMTOT);
    dot_interact_mma<<<grid, THREADS, SMEMTOT>>>(dense4, sparse4, out, B);
    (void)n_in; (void)out_size;
}